// round 8
// baseline (speedup 1.0000x reference)
#include <cuda_runtime.h>
#include <cuda_bf16.h>
#include <cstdint>

// Problem constants
constexpr int N_NODES = 50000;
constexpr int E_EDGES = 800000;
constexpr int IN_DIM  = 128;
constexpr int OUT_DIM = 128;
constexpr int R_REL   = 8;
constexpr int K_DIM   = IN_DIM * (R_REL + 1);   // 1152
constexpr int KC      = 32;                      // K per chunk
constexpr int NCHUNK  = K_DIM / KC;              // 36
constexpr int MAXDEG  = 64;                      // Poisson(4); ample

// H / W^T storage: per (row, chunk) one 128B block = [hi 32 bf16 | lo 32 bf16]
__device__ uint32_t g_cnt[R_REL * N_NODES];                      // 1.6 MB
__device__ uint32_t g_idx[(size_t)R_REL * N_NODES * MAXDEG];     // 102.4 MB
__device__ __nv_bfloat16 g_h [(size_t)N_NODES * K_DIM * 2];      // 230 MB
__device__ __nv_bfloat16 g_bt[(size_t)OUT_DIM * K_DIM * 2];      // 0.6 MB

// ---------------------------------------------------------------------------
// Kernel 1: zero per-segment counters
// ---------------------------------------------------------------------------
__global__ void zero_cnt_kernel() {
    const int i = blockIdx.x * blockDim.x + threadIdx.x;
    if (i < R_REL * N_NODES) g_cnt[i] = 0u;
}

// ---------------------------------------------------------------------------
// Kernel 2: W^T -> blocked bf16 hi/lo.  BT[n][k] = Wcat[k][n]
// ---------------------------------------------------------------------------
__global__ void convert_w_kernel(const float* __restrict__ weight,
                                 const float* __restrict__ selfw) {
    const int idx = blockIdx.x * blockDim.x + threadIdx.x;
    if (idx >= OUT_DIM * K_DIM) return;
    const int n = idx / K_DIM;
    const int k = idx % K_DIM;
    const float v = (k < IN_DIM)
        ? selfw[(size_t)k * OUT_DIM + n]
        : weight[(size_t)(k - IN_DIM) * OUT_DIM + n];
    const __nv_bfloat16 hi = __float2bfloat16(v);
    const __nv_bfloat16 lo = __float2bfloat16(v - __bfloat162float(hi));
    const int c = k / KC, p = k % KC;
    __nv_bfloat16* blk = g_bt + ((size_t)n * NCHUNK + c) * 64;
    blk[p]      = hi;
    blk[32 + p] = lo;
}

// ---------------------------------------------------------------------------
// Kernel 3: bucket build (both directed messages per undirected edge)
// ---------------------------------------------------------------------------
__global__ void fill_kernel(const int* __restrict__ ei,
                            const int* __restrict__ et) {
    const int e = blockIdx.x * blockDim.x + threadIdx.x;
    if (e >= E_EDGES) return;
    const int src = ei[e];
    const int dst = ei[E_EDGES + e];
    const int r   = et[e];

    const int seg1 = r * N_NODES + dst;
    uint32_t p1 = atomicAdd(&g_cnt[seg1], 1u);
    if (p1 < MAXDEG) g_idx[(size_t)seg1 * MAXDEG + p1] = (uint32_t)src;

    const int seg2 = r * N_NODES + src;
    uint32_t p2 = atomicAdd(&g_cnt[seg2], 1u);
    if (p2 < MAXDEG) g_idx[(size_t)seg2 * MAXDEG + p2] = (uint32_t)dst;
}

// ---------------------------------------------------------------------------
// Kernel 4: aggregate.  One warp per (v, r9) segment; r9=0 -> x itself,
// r9=1..8 -> mean over relation-(r9-1) neighbors.  4-way unrolled gather
// (4 independent accumulators -> MLP=4).  Writes H blocked bf16 hi/lo.
// ---------------------------------------------------------------------------
__global__ __launch_bounds__(256)
void agg_kernel(const float* __restrict__ x) {
    const int w = blockIdx.x * 8 + (threadIdx.x >> 5);
    if (w >= N_NODES * 9) return;
    const int lane = threadIdx.x & 31;
    const int v  = w / 9;
    const int r9 = w - v * 9;

    const float4* __restrict__ x4 = reinterpret_cast<const float4*>(x);
    float4 acc = make_float4(0.f, 0.f, 0.f, 0.f);
    float  sc;

    if (r9 == 0) {
        acc = x4[(size_t)v * 32 + lane];
        sc  = 1.0f;
    } else {
        const int seg = (r9 - 1) * N_NODES + v;
        const uint32_t cnt = g_cnt[seg];
        const int d = (cnt < MAXDEG) ? (int)cnt : MAXDEG;
        const uint32_t* __restrict__ lst = g_idx + (size_t)seg * MAXDEG;

        float4 a0 = make_float4(0.f, 0.f, 0.f, 0.f);
        float4 a1 = a0, a2 = a0, a3 = a0;
        int j = 0;
        for (; j + 4 <= d; j += 4) {
            const uint32_t i0 = lst[j], i1 = lst[j + 1],
                           i2 = lst[j + 2], i3 = lst[j + 3];
            const float4 t0 = x4[(size_t)i0 * 32 + lane];
            const float4 t1 = x4[(size_t)i1 * 32 + lane];
            const float4 t2 = x4[(size_t)i2 * 32 + lane];
            const float4 t3 = x4[(size_t)i3 * 32 + lane];
            a0.x += t0.x; a0.y += t0.y; a0.z += t0.z; a0.w += t0.w;
            a1.x += t1.x; a1.y += t1.y; a1.z += t1.z; a1.w += t1.w;
            a2.x += t2.x; a2.y += t2.y; a2.z += t2.z; a2.w += t2.w;
            a3.x += t3.x; a3.y += t3.y; a3.z += t3.z; a3.w += t3.w;
        }
        for (; j < d; j++) {
            const float4 t = x4[(size_t)lst[j] * 32 + lane];
            a0.x += t.x; a0.y += t.y; a0.z += t.z; a0.w += t.w;
        }
        acc.x = (a0.x + a1.x) + (a2.x + a3.x);
        acc.y = (a0.y + a1.y) + (a2.y + a3.y);
        acc.z = (a0.z + a1.z) + (a2.z + a3.z);
        acc.w = (a0.w + a1.w) + (a2.w + a3.w);
        sc = (cnt > 0u) ? (1.0f / (float)cnt) : 0.0f;
    }

    const float f0 = acc.x * sc, f1 = acc.y * sc, f2 = acc.z * sc, f3 = acc.w * sc;
    const __nv_bfloat162 h01 = __floats2bfloat162_rn(f0, f1);
    const __nv_bfloat162 h23 = __floats2bfloat162_rn(f2, f3);
    const __nv_bfloat162 l01 = __floats2bfloat162_rn(
        f0 - __bfloat162float(h01.x), f1 - __bfloat162float(h01.y));
    const __nv_bfloat162 l23 = __floats2bfloat162_rn(
        f2 - __bfloat162float(h23.x), f3 - __bfloat162float(h23.y));

    const int c   = r9 * 4 + (lane >> 3);        // chunk index
    const int off = (lane & 7) * 4;              // element within chunk
    __nv_bfloat16* blk = g_h + ((size_t)v * NCHUNK + c) * 64;
    *reinterpret_cast<__nv_bfloat162*>(blk + off)          = h01;
    *reinterpret_cast<__nv_bfloat162*>(blk + off + 2)      = h23;
    *reinterpret_cast<__nv_bfloat162*>(blk + 32 + off)     = l01;
    *reinterpret_cast<__nv_bfloat162*>(blk + 32 + off + 2) = l23;
}

// ---------------------------------------------------------------------------
// mma.sync / cp.async helpers
// ---------------------------------------------------------------------------
__device__ __forceinline__ uint32_t smem_u32(const void* p) {
    uint32_t a;
    asm("{ .reg .u64 t; cvta.to.shared.u64 t, %1; cvt.u32.u64 %0, t; }"
        : "=r"(a) : "l"(p));
    return a;
}
__device__ __forceinline__ uint64_t gmem_u64(const void* p) {
    uint64_t a;
    asm("cvta.to.global.u64 %0, %1;" : "=l"(a) : "l"(p));
    return a;
}
__device__ __forceinline__ uint32_t sw128(uint32_t o) {
    return o ^ ((o >> 3) & 0x70);
}
__device__ __forceinline__ void cp16(uint32_t dst, uint64_t src) {
    asm volatile("cp.async.cg.shared.global [%0], [%1], 16;"
                 :: "r"(dst), "l"(src) : "memory");
}
__device__ __forceinline__ void cp_commit() {
    asm volatile("cp.async.commit_group;" ::: "memory");
}
template<int n> __device__ __forceinline__ void cp_wait() {
    asm volatile("cp.async.wait_group %0;" :: "n"(n) : "memory");
}
__device__ __forceinline__ void ldsm_x4(uint32_t addr,
                                        uint32_t& r0, uint32_t& r1,
                                        uint32_t& r2, uint32_t& r3) {
    asm volatile("ldmatrix.sync.aligned.m8n8.x4.shared.b16 {%0,%1,%2,%3}, [%4];"
                 : "=r"(r0), "=r"(r1), "=r"(r2), "=r"(r3) : "r"(addr));
}
__device__ __forceinline__ void mma16816(float* c, const uint32_t* a,
                                         uint32_t b0, uint32_t b1) {
    asm volatile(
        "mma.sync.aligned.m16n8k16.row.col.f32.bf16.bf16.f32 "
        "{%0,%1,%2,%3}, {%4,%5,%6,%7}, {%8,%9}, {%0,%1,%2,%3};"
        : "+f"(c[0]), "+f"(c[1]), "+f"(c[2]), "+f"(c[3])
        : "r"(a[0]), "r"(a[1]), "r"(a[2]), "r"(a[3]), "r"(b0), "r"(b1));
}

// Smem: 3 stages x {A tile 16KB, B tile 16KB}. Tile row = 128B [hi64B|lo64B].
constexpr int STAGE   = 32768;
constexpr int OFF_B   = 16384;
constexpr int SMEM_TOTAL = 3 * STAGE;   // 96 KB -> 2 CTAs/SM

// ---------------------------------------------------------------------------
// Kernel 5: out = H @ Wcat, pure bf16 3-split GEMM (hi*hi + hi*lo + lo*hi).
// CTA 128x128, 8 warps (4x2), KC=32, 3-stage cp.async ring, ONE sync/iter.
// ---------------------------------------------------------------------------
__global__ __launch_bounds__(256, 2)
void gemm_kernel(float* __restrict__ out) {
    extern __shared__ char smem[];
    const uint32_t sb = smem_u32(smem);
    const int tid  = threadIdx.x;
    const int wid  = tid >> 5;
    const int lane = tid & 31;
    const int m0   = blockIdx.x * 128;

    const int wm = wid & 3, wn = wid >> 2;
    const int mbase = wm * 32, nbase = wn * 64;
    const int rlane = lane & 15;
    const int klane = (lane >> 4) * 16;

    // cp.async mapping: 2 threads/row, each one 64B half (4x cp16)
    const int crow = tid >> 1;
    const int chalf = (tid & 1) * 64;
    const int arow = (m0 + crow < N_NODES) ? (m0 + crow) : (N_NODES - 1);
    const uint64_t gA = gmem_u64(g_h)  + ((size_t)arow * NCHUNK) * 128 + chalf;
    const uint64_t gB = gmem_u64(g_bt) + ((size_t)crow * NCHUNK) * 128 + chalf;
    const uint32_t rowbase = (uint32_t)(crow * 128 + chalf);

    auto issue = [&](int ch, int s) {
        const uint32_t da = sb + s * STAGE;
        const uint32_t db = da + OFF_B;
        const uint64_t sa = gA + (size_t)ch * 128;
        const uint64_t sbsrc = gB + (size_t)ch * 128;
        // swizzle applied PER 16-byte transfer (matches ldmatrix side)
        #pragma unroll
        for (int i = 0; i < 4; i++) cp16(da + sw128(rowbase + i * 16), sa + i * 16);
        #pragma unroll
        for (int i = 0; i < 4; i++) cp16(db + sw128(rowbase + i * 16), sbsrc + i * 16);
        cp_commit();
    };

    float acc[2][8][4];
    #pragma unroll
    for (int i = 0; i < 2; i++)
        #pragma unroll
        for (int j = 0; j < 8; j++)
            #pragma unroll
            for (int q = 0; q < 4; q++) acc[i][j][q] = 0.f;

    issue(0, 0);
    issue(1, 1);

    for (int ch = 0; ch < NCHUNK; ch++) {
        // Wait for stage ch (allow the next group to stay in flight), then a
        // single barrier: (a) makes stage-ch data visible to all warps,
        // (b) proves all warps finished reading stage (ch-1)%3, which is the
        // stage issue(ch+2) overwrites below.
        if (ch + 1 < NCHUNK) cp_wait<1>(); else cp_wait<0>();
        __syncthreads();
        if (ch + 2 < NCHUNK) issue(ch + 2, (ch + 2) % 3);

        const uint32_t sA = sb + (ch % 3) * STAGE;
        const uint32_t sB = sA + OFF_B;
        #pragma unroll
        for (int kk = 0; kk < 2; kk++) {
            const uint32_t kb = (uint32_t)(kk * 32 + klane);
            uint32_t ahi[2][4], alo[2][4];
            #pragma unroll
            for (int g = 0; g < 2; g++) {
                const uint32_t ro = (uint32_t)((mbase + g * 16 + rlane) * 128);
                ldsm_x4(sA + sw128(ro + kb),      ahi[g][0], ahi[g][1], ahi[g][2], ahi[g][3]);
                ldsm_x4(sA + sw128(ro + 64 + kb), alo[g][0], alo[g][1], alo[g][2], alo[g][3]);
            }
            uint32_t b[4][4];
            #pragma unroll
            for (int nt = 0; nt < 4; nt++) {
                const uint32_t ro = (uint32_t)((nbase + nt * 16 + rlane) * 128);
                ldsm_x4(sB + sw128(ro + kb), b[nt][0], b[nt][1], b[nt][2], b[nt][3]);
            }
            #pragma unroll
            for (int g = 0; g < 2; g++)
                #pragma unroll
                for (int nt = 0; nt < 4; nt++) {
                    mma16816(acc[g][nt * 2 + 0], ahi[g], b[nt][0], b[nt][2]);
                    mma16816(acc[g][nt * 2 + 1], ahi[g], b[nt][1], b[nt][3]);
                    mma16816(acc[g][nt * 2 + 0], alo[g], b[nt][0], b[nt][2]);
                    mma16816(acc[g][nt * 2 + 1], alo[g], b[nt][1], b[nt][3]);
                }
            #pragma unroll
            for (int nt = 0; nt < 4; nt++) {
                const uint32_t ro = (uint32_t)((nbase + nt * 16 + rlane) * 128);
                ldsm_x4(sB + sw128(ro + 64 + kb), b[nt][0], b[nt][1], b[nt][2], b[nt][3]);
            }
            #pragma unroll
            for (int g = 0; g < 2; g++)
                #pragma unroll
                for (int nt = 0; nt < 4; nt++) {
                    mma16816(acc[g][nt * 2 + 0], ahi[g], b[nt][0], b[nt][2]);
                    mma16816(acc[g][nt * 2 + 1], ahi[g], b[nt][1], b[nt][3]);
                }
        }
    }

    // ---- epilogue ----
    const int gq = lane >> 2;
    const int tq = lane & 3;
    #pragma unroll
    for (int g = 0; g < 2; g++) {
        const int row_lo = m0 + mbase + g * 16 + gq;
        const int row_hi = row_lo + 8;
        #pragma unroll
        for (int nt = 0; nt < 8; nt++) {
            const int col = nbase + nt * 8 + tq * 2;
            if (row_lo < N_NODES)
                *reinterpret_cast<float2*>(out + (size_t)row_lo * OUT_DIM + col) =
                    make_float2(acc[g][nt][0], acc[g][nt][1]);
            if (row_hi < N_NODES)
                *reinterpret_cast<float2*>(out + (size_t)row_hi * OUT_DIM + col) =
                    make_float2(acc[g][nt][2], acc[g][nt][3]);
        }
    }
}

// ---------------------------------------------------------------------------
// Launch
// ---------------------------------------------------------------------------
extern "C" void kernel_launch(void* const* d_in, const int* in_sizes, int n_in,
                              void* d_out, int out_size) {
    const float* x      = (const float*)d_in[0];
    const float* weight = (const float*)d_in[1];
    const float* selfw  = (const float*)d_in[2];
    const int*   ei     = (const int*)d_in[3];
    const int*   et     = (const int*)d_in[4];
    float*       out    = (float*)d_out;

    cudaFuncSetAttribute(gemm_kernel,
                         cudaFuncAttributeMaxDynamicSharedMemorySize, SMEM_TOTAL);

    zero_cnt_kernel<<<(R_REL * N_NODES + 255) / 256, 256>>>();
    convert_w_kernel<<<(OUT_DIM * K_DIM + 255) / 256, 256>>>(weight, selfw);
    fill_kernel<<<(E_EDGES + 255) / 256, 256>>>(ei, et);

    const int segs = N_NODES * 9;                       // 450000 warps
    agg_kernel<<<(segs + 7) / 8, 256>>>(x);

    gemm_kernel<<<(N_NODES + 127) / 128, 256, SMEM_TOTAL>>>(out);
}

// round 9
// speedup vs baseline: 1.1092x; 1.1092x over previous
#include <cuda_runtime.h>
#include <cuda_bf16.h>
#include <cstdint>

// Problem constants
constexpr int N_NODES = 50000;
constexpr int E_EDGES = 800000;
constexpr int IN_DIM  = 128;
constexpr int OUT_DIM = 128;
constexpr int R_REL   = 8;
constexpr int K_DIM   = IN_DIM * (R_REL + 1);   // 1152
constexpr int KC      = 32;                      // K per chunk
constexpr int NCHUNK  = K_DIM / KC;              // 36
constexpr int MAXDEG  = 64;                      // Poisson(4); ample

// H / W^T storage: per (row, chunk) one 128B block = [hi 32 bf16 | lo 32 bf16]
__device__ uint32_t g_cnt[R_REL * N_NODES];                      // 1.6 MB
__device__ uint32_t g_idx[(size_t)R_REL * N_NODES * MAXDEG];     // 102.4 MB
__device__ __nv_bfloat16 g_h [(size_t)N_NODES * K_DIM * 2];      // 230 MB
__device__ __nv_bfloat16 g_bt[(size_t)OUT_DIM * K_DIM * 2];      // 0.6 MB

// ---------------------------------------------------------------------------
// Kernel 1: zero per-segment counters
// ---------------------------------------------------------------------------
__global__ void zero_cnt_kernel() {
    const int i = blockIdx.x * blockDim.x + threadIdx.x;
    if (i < R_REL * N_NODES) g_cnt[i] = 0u;
}

// ---------------------------------------------------------------------------
// Kernel 2: W^T -> blocked bf16 hi/lo.  BT[n][k] = Wcat[k][n]
// ---------------------------------------------------------------------------
__global__ void convert_w_kernel(const float* __restrict__ weight,
                                 const float* __restrict__ selfw) {
    const int idx = blockIdx.x * blockDim.x + threadIdx.x;
    if (idx >= OUT_DIM * K_DIM) return;
    const int n = idx / K_DIM;
    const int k = idx % K_DIM;
    const float v = (k < IN_DIM)
        ? selfw[(size_t)k * OUT_DIM + n]
        : weight[(size_t)(k - IN_DIM) * OUT_DIM + n];
    const __nv_bfloat16 hi = __float2bfloat16(v);
    const __nv_bfloat16 lo = __float2bfloat16(v - __bfloat162float(hi));
    const int c = k / KC, p = k % KC;
    __nv_bfloat16* blk = g_bt + ((size_t)n * NCHUNK + c) * 64;
    blk[p]      = hi;
    blk[32 + p] = lo;
}

// ---------------------------------------------------------------------------
// Kernel 3: bucket build (both directed messages per undirected edge)
// ---------------------------------------------------------------------------
__global__ void fill_kernel(const int* __restrict__ ei,
                            const int* __restrict__ et) {
    const int e = blockIdx.x * blockDim.x + threadIdx.x;
    if (e >= E_EDGES) return;
    const int src = ei[e];
    const int dst = ei[E_EDGES + e];
    const int r   = et[e];

    const int seg1 = r * N_NODES + dst;
    uint32_t p1 = atomicAdd(&g_cnt[seg1], 1u);
    if (p1 < MAXDEG) g_idx[(size_t)seg1 * MAXDEG + p1] = (uint32_t)src;

    const int seg2 = r * N_NODES + src;
    uint32_t p2 = atomicAdd(&g_cnt[seg2], 1u);
    if (p2 < MAXDEG) g_idx[(size_t)seg2 * MAXDEG + p2] = (uint32_t)dst;
}

// ---------------------------------------------------------------------------
// Kernel 4: aggregate.  One warp per (v, r9) segment; r9=0 -> x itself,
// r9=1..8 -> mean over relation-(r9-1) neighbors.  Simple gather loop
// (round-7 form: 32 regs, max occupancy — occupancy IS the MLP here).
// ---------------------------------------------------------------------------
__global__ __launch_bounds__(256)
void agg_kernel(const float* __restrict__ x) {
    const int w = blockIdx.x * 8 + (threadIdx.x >> 5);
    if (w >= N_NODES * 9) return;
    const int lane = threadIdx.x & 31;
    const int v  = w / 9;
    const int r9 = w - v * 9;

    const float4* __restrict__ x4 = reinterpret_cast<const float4*>(x);
    float4 acc = make_float4(0.f, 0.f, 0.f, 0.f);
    float  sc;

    if (r9 == 0) {
        acc = x4[(size_t)v * 32 + lane];
        sc  = 1.0f;
    } else {
        const int seg = (r9 - 1) * N_NODES + v;
        const uint32_t cnt = g_cnt[seg];
        const int d = (cnt < MAXDEG) ? (int)cnt : MAXDEG;
        const uint32_t* __restrict__ lst = g_idx + (size_t)seg * MAXDEG;
        for (int j = 0; j < d; j++) {
            const float4 t = x4[(size_t)lst[j] * 32 + lane];
            acc.x += t.x; acc.y += t.y; acc.z += t.z; acc.w += t.w;
        }
        sc = (cnt > 0u) ? (1.0f / (float)cnt) : 0.0f;
    }

    const float f0 = acc.x * sc, f1 = acc.y * sc, f2 = acc.z * sc, f3 = acc.w * sc;
    const __nv_bfloat162 h01 = __floats2bfloat162_rn(f0, f1);
    const __nv_bfloat162 h23 = __floats2bfloat162_rn(f2, f3);
    const __nv_bfloat162 l01 = __floats2bfloat162_rn(
        f0 - __bfloat162float(h01.x), f1 - __bfloat162float(h01.y));
    const __nv_bfloat162 l23 = __floats2bfloat162_rn(
        f2 - __bfloat162float(h23.x), f3 - __bfloat162float(h23.y));

    const int c   = r9 * 4 + (lane >> 3);        // chunk index
    const int off = (lane & 7) * 4;              // element within chunk
    __nv_bfloat16* blk = g_h + ((size_t)v * NCHUNK + c) * 64;
    *reinterpret_cast<__nv_bfloat162*>(blk + off)          = h01;
    *reinterpret_cast<__nv_bfloat162*>(blk + off + 2)      = h23;
    *reinterpret_cast<__nv_bfloat162*>(blk + 32 + off)     = l01;
    *reinterpret_cast<__nv_bfloat162*>(blk + 32 + off + 2) = l23;
}

// ---------------------------------------------------------------------------
// mma.sync / cp.async helpers
// ---------------------------------------------------------------------------
__device__ __forceinline__ uint32_t smem_u32(const void* p) {
    uint32_t a;
    asm("{ .reg .u64 t; cvta.to.shared.u64 t, %1; cvt.u32.u64 %0, t; }"
        : "=r"(a) : "l"(p));
    return a;
}
__device__ __forceinline__ uint64_t gmem_u64(const void* p) {
    uint64_t a;
    asm("cvta.to.global.u64 %0, %1;" : "=l"(a) : "l"(p));
    return a;
}
__device__ __forceinline__ uint32_t sw128(uint32_t o) {
    return o ^ ((o >> 3) & 0x70);
}
__device__ __forceinline__ void cp16(uint32_t dst, uint64_t src) {
    asm volatile("cp.async.cg.shared.global [%0], [%1], 16;"
                 :: "r"(dst), "l"(src) : "memory");
}
__device__ __forceinline__ void cp_commit() {
    asm volatile("cp.async.commit_group;" ::: "memory");
}
template<int n> __device__ __forceinline__ void cp_wait() {
    asm volatile("cp.async.wait_group %0;" :: "n"(n) : "memory");
}
__device__ __forceinline__ void ldsm_x4(uint32_t addr,
                                        uint32_t& r0, uint32_t& r1,
                                        uint32_t& r2, uint32_t& r3) {
    asm volatile("ldmatrix.sync.aligned.m8n8.x4.shared.b16 {%0,%1,%2,%3}, [%4];"
                 : "=r"(r0), "=r"(r1), "=r"(r2), "=r"(r3) : "r"(addr));
}
__device__ __forceinline__ void mma16816(float* c, const uint32_t* a,
                                         uint32_t b0, uint32_t b1) {
    asm volatile(
        "mma.sync.aligned.m16n8k16.row.col.f32.bf16.bf16.f32 "
        "{%0,%1,%2,%3}, {%4,%5,%6,%7}, {%8,%9}, {%0,%1,%2,%3};"
        : "+f"(c[0]), "+f"(c[1]), "+f"(c[2]), "+f"(c[3])
        : "r"(a[0]), "r"(a[1]), "r"(a[2]), "r"(a[3]), "r"(b0), "r"(b1));
}

// Smem: 3 stages x {A tile 16KB, B tile 16KB}. Tile row = 128B [hi64B|lo64B].
constexpr int STAGE   = 32768;
constexpr int OFF_B   = 16384;
constexpr int SMEM_TOTAL = 3 * STAGE;   // 96 KB -> 2 CTAs/SM

// ---------------------------------------------------------------------------
// Kernel 5: out = H @ Wcat, pure bf16 3-split GEMM (hi*hi + lo*hi + hi*lo).
// CTA 128x128, 8 warps (4x2), KC=32, 3-stage cp.async ring, ONE sync/iter.
// MMA schedule in 3 passes of 16 distinct-accumulator MMAs -> RAW distance 16.
// ---------------------------------------------------------------------------
__global__ __launch_bounds__(256, 2)
void gemm_kernel(float* __restrict__ out) {
    extern __shared__ char smem[];
    const uint32_t sb = smem_u32(smem);
    const int tid  = threadIdx.x;
    const int wid  = tid >> 5;
    const int lane = tid & 31;
    const int m0   = blockIdx.x * 128;

    const int wm = wid & 3, wn = wid >> 2;
    const int mbase = wm * 32, nbase = wn * 64;
    const int rlane = lane & 15;
    const int klane = (lane >> 4) * 16;

    // cp.async mapping: 2 threads/row, each one 64B half (4x cp16)
    const int crow = tid >> 1;
    const int chalf = (tid & 1) * 64;
    const int arow = (m0 + crow < N_NODES) ? (m0 + crow) : (N_NODES - 1);
    const uint64_t gA = gmem_u64(g_h)  + ((size_t)arow * NCHUNK) * 128 + chalf;
    const uint64_t gB = gmem_u64(g_bt) + ((size_t)crow * NCHUNK) * 128 + chalf;
    const uint32_t rowbase = (uint32_t)(crow * 128 + chalf);

    auto issue = [&](int ch, int s) {
        const uint32_t da = sb + s * STAGE;
        const uint32_t db = da + OFF_B;
        const uint64_t sa = gA + (size_t)ch * 128;
        const uint64_t sbsrc = gB + (size_t)ch * 128;
        // swizzle applied PER 16-byte transfer (matches ldmatrix side)
        #pragma unroll
        for (int i = 0; i < 4; i++) cp16(da + sw128(rowbase + i * 16), sa + i * 16);
        #pragma unroll
        for (int i = 0; i < 4; i++) cp16(db + sw128(rowbase + i * 16), sbsrc + i * 16);
        cp_commit();
    };

    float acc[2][8][4];
    #pragma unroll
    for (int i = 0; i < 2; i++)
        #pragma unroll
        for (int j = 0; j < 8; j++)
            #pragma unroll
            for (int q = 0; q < 4; q++) acc[i][j][q] = 0.f;

    issue(0, 0);
    issue(1, 1);

    for (int ch = 0; ch < NCHUNK; ch++) {
        // One barrier per iter: makes stage-ch data visible AND proves all
        // warps are done reading the stage issue(ch+2) will overwrite.
        if (ch + 1 < NCHUNK) cp_wait<1>(); else cp_wait<0>();
        __syncthreads();
        if (ch + 2 < NCHUNK) issue(ch + 2, (ch + 2) % 3);

        const uint32_t sA = sb + (ch % 3) * STAGE;
        const uint32_t sB = sA + OFF_B;
        #pragma unroll
        for (int kk = 0; kk < 2; kk++) {
            const uint32_t kb = (uint32_t)(kk * 32 + klane);
            uint32_t ahi[2][4], alo[2][4];
            #pragma unroll
            for (int g = 0; g < 2; g++) {
                const uint32_t ro = (uint32_t)((mbase + g * 16 + rlane) * 128);
                ldsm_x4(sA + sw128(ro + kb),      ahi[g][0], ahi[g][1], ahi[g][2], ahi[g][3]);
                ldsm_x4(sA + sw128(ro + 64 + kb), alo[g][0], alo[g][1], alo[g][2], alo[g][3]);
            }
            uint32_t b[4][4];
            #pragma unroll
            for (int nt = 0; nt < 4; nt++) {
                const uint32_t ro = (uint32_t)((nbase + nt * 16 + rlane) * 128);
                ldsm_x4(sB + sw128(ro + kb), b[nt][0], b[nt][1], b[nt][2], b[nt][3]);
            }
            // pass 1: hi*hi  (16 MMAs, all distinct accumulators)
            #pragma unroll
            for (int g = 0; g < 2; g++)
                #pragma unroll
                for (int nt = 0; nt < 4; nt++) {
                    mma16816(acc[g][nt * 2 + 0], ahi[g], b[nt][0], b[nt][2]);
                    mma16816(acc[g][nt * 2 + 1], ahi[g], b[nt][1], b[nt][3]);
                }
            // pass 2: lo*hi  (RAW distance 16 vs pass 1)
            #pragma unroll
            for (int g = 0; g < 2; g++)
                #pragma unroll
                for (int nt = 0; nt < 4; nt++) {
                    mma16816(acc[g][nt * 2 + 0], alo[g], b[nt][0], b[nt][2]);
                    mma16816(acc[g][nt * 2 + 1], alo[g], b[nt][1], b[nt][3]);
                }
            // load B_lo, pass 3: hi*lo
            #pragma unroll
            for (int nt = 0; nt < 4; nt++) {
                const uint32_t ro = (uint32_t)((nbase + nt * 16 + rlane) * 128);
                ldsm_x4(sB + sw128(ro + 64 + kb), b[nt][0], b[nt][1], b[nt][2], b[nt][3]);
            }
            #pragma unroll
            for (int g = 0; g < 2; g++)
                #pragma unroll
                for (int nt = 0; nt < 4; nt++) {
                    mma16816(acc[g][nt * 2 + 0], ahi[g], b[nt][0], b[nt][2]);
                    mma16816(acc[g][nt * 2 + 1], ahi[g], b[nt][1], b[nt][3]);
                }
        }
    }

    // ---- epilogue ----
    const int gq = lane >> 2;
    const int tq = lane & 3;
    #pragma unroll
    for (int g = 0; g < 2; g++) {
        const int row_lo = m0 + mbase + g * 16 + gq;
        const int row_hi = row_lo + 8;
        #pragma unroll
        for (int nt = 0; nt < 8; nt++) {
            const int col = nbase + nt * 8 + tq * 2;
            if (row_lo < N_NODES)
                *reinterpret_cast<float2*>(out + (size_t)row_lo * OUT_DIM + col) =
                    make_float2(acc[g][nt][0], acc[g][nt][1]);
            if (row_hi < N_NODES)
                *reinterpret_cast<float2*>(out + (size_t)row_hi * OUT_DIM + col) =
                    make_float2(acc[g][nt][2], acc[g][nt][3]);
        }
    }
}

// ---------------------------------------------------------------------------
// Launch
// ---------------------------------------------------------------------------
extern "C" void kernel_launch(void* const* d_in, const int* in_sizes, int n_in,
                              void* d_out, int out_size) {
    const float* x      = (const float*)d_in[0];
    const float* weight = (const float*)d_in[1];
    const float* selfw  = (const float*)d_in[2];
    const int*   ei     = (const int*)d_in[3];
    const int*   et     = (const int*)d_in[4];
    float*       out    = (float*)d_out;

    cudaFuncSetAttribute(gemm_kernel,
                         cudaFuncAttributeMaxDynamicSharedMemorySize, SMEM_TOTAL);

    zero_cnt_kernel<<<(R_REL * N_NODES + 255) / 256, 256>>>();
    convert_w_kernel<<<(OUT_DIM * K_DIM + 255) / 256, 256>>>(weight, selfw);
    fill_kernel<<<(E_EDGES + 255) / 256, 256>>>(ei, et);

    const int segs = N_NODES * 9;                       // 450000 warps
    agg_kernel<<<(segs + 7) / 8, 256>>>(x);

    gemm_kernel<<<(N_NODES + 127) / 128, 256, SMEM_TOTAL>>>(out);
}

// round 10
// speedup vs baseline: 1.2791x; 1.1532x over previous
#include <cuda_runtime.h>
#include <cuda_fp16.h>
#include <cstdint>

// Problem constants
constexpr int N_NODES = 50000;
constexpr int E_EDGES = 800000;
constexpr int IN_DIM  = 128;
constexpr int OUT_DIM = 128;
constexpr int R_REL   = 8;
constexpr int K_DIM   = IN_DIM * (R_REL + 1);   // 1152
constexpr int KC      = 32;                      // K per chunk
constexpr int NCHUNK  = K_DIM / KC;              // 36
constexpr int MAXDEG  = 64;                      // Poisson(4); ample

// H / W^T storage: per (row, chunk) one 128B block = [hi 32 fp16 | lo 32 fp16]
__device__ uint32_t g_cnt[R_REL * N_NODES];                      // 1.6 MB
__device__ uint32_t g_idx[(size_t)R_REL * N_NODES * MAXDEG];     // 102.4 MB
__device__ __half g_h [(size_t)N_NODES * K_DIM * 2];             // 230 MB
__device__ __half g_bt[(size_t)OUT_DIM * K_DIM * 2];             // 0.6 MB

// ---------------------------------------------------------------------------
// Kernel 1: zero per-segment counters
// ---------------------------------------------------------------------------
__global__ void zero_cnt_kernel() {
    const int i = blockIdx.x * blockDim.x + threadIdx.x;
    if (i < R_REL * N_NODES) g_cnt[i] = 0u;
}

// ---------------------------------------------------------------------------
// Kernel 2: W^T -> blocked fp16 hi/lo.  BT[n][k] = Wcat[k][n]
// ---------------------------------------------------------------------------
__global__ void convert_w_kernel(const float* __restrict__ weight,
                                 const float* __restrict__ selfw) {
    const int idx = blockIdx.x * blockDim.x + threadIdx.x;
    if (idx >= OUT_DIM * K_DIM) return;
    const int n = idx / K_DIM;
    const int k = idx % K_DIM;
    const float v = (k < IN_DIM)
        ? selfw[(size_t)k * OUT_DIM + n]
        : weight[(size_t)(k - IN_DIM) * OUT_DIM + n];
    const __half hi = __float2half_rn(v);
    const __half lo = __float2half_rn(v - __half2float(hi));
    const int c = k / KC, p = k % KC;
    __half* blk = g_bt + ((size_t)n * NCHUNK + c) * 64;
    blk[p]      = hi;
    blk[32 + p] = lo;   // kept for possible 3-term revert; gemm ignores it
}

// ---------------------------------------------------------------------------
// Kernel 3: bucket build (both directed messages per undirected edge)
// ---------------------------------------------------------------------------
__global__ void fill_kernel(const int* __restrict__ ei,
                            const int* __restrict__ et) {
    const int e = blockIdx.x * blockDim.x + threadIdx.x;
    if (e >= E_EDGES) return;
    const int src = ei[e];
    const int dst = ei[E_EDGES + e];
    const int r   = et[e];

    const int seg1 = r * N_NODES + dst;
    uint32_t p1 = atomicAdd(&g_cnt[seg1], 1u);
    if (p1 < MAXDEG) g_idx[(size_t)seg1 * MAXDEG + p1] = (uint32_t)src;

    const int seg2 = r * N_NODES + src;
    uint32_t p2 = atomicAdd(&g_cnt[seg2], 1u);
    if (p2 < MAXDEG) g_idx[(size_t)seg2 * MAXDEG + p2] = (uint32_t)dst;
}

// ---------------------------------------------------------------------------
// Kernel 4: aggregate.  One warp per (v, r9) segment; r9=0 -> x itself,
// r9=1..8 -> mean over relation-(r9-1) neighbors.  Simple gather loop
// (32 regs, max occupancy — occupancy IS the MLP here).  Emits fp16 hi/lo.
// ---------------------------------------------------------------------------
__global__ __launch_bounds__(256)
void agg_kernel(const float* __restrict__ x) {
    const int w = blockIdx.x * 8 + (threadIdx.x >> 5);
    if (w >= N_NODES * 9) return;
    const int lane = threadIdx.x & 31;
    const int v  = w / 9;
    const int r9 = w - v * 9;

    const float4* __restrict__ x4 = reinterpret_cast<const float4*>(x);
    float4 acc = make_float4(0.f, 0.f, 0.f, 0.f);
    float  sc;

    if (r9 == 0) {
        acc = x4[(size_t)v * 32 + lane];
        sc  = 1.0f;
    } else {
        const int seg = (r9 - 1) * N_NODES + v;
        const uint32_t cnt = g_cnt[seg];
        const int d = (cnt < MAXDEG) ? (int)cnt : MAXDEG;
        const uint32_t* __restrict__ lst = g_idx + (size_t)seg * MAXDEG;
        for (int j = 0; j < d; j++) {
            const float4 t = x4[(size_t)lst[j] * 32 + lane];
            acc.x += t.x; acc.y += t.y; acc.z += t.z; acc.w += t.w;
        }
        sc = (cnt > 0u) ? (1.0f / (float)cnt) : 0.0f;
    }

    const float f0 = acc.x * sc, f1 = acc.y * sc, f2 = acc.z * sc, f3 = acc.w * sc;
    const __half2 h01 = __floats2half2_rn(f0, f1);
    const __half2 h23 = __floats2half2_rn(f2, f3);
    const __half2 l01 = __floats2half2_rn(f0 - __low2float(h01),
                                          f1 - __high2float(h01));
    const __half2 l23 = __floats2half2_rn(f2 - __low2float(h23),
                                          f3 - __high2float(h23));

    const int c   = r9 * 4 + (lane >> 3);        // chunk index
    const int off = (lane & 7) * 4;              // element within chunk
    __half* blk = g_h + ((size_t)v * NCHUNK + c) * 64;
    *reinterpret_cast<__half2*>(blk + off)          = h01;
    *reinterpret_cast<__half2*>(blk + off + 2)      = h23;
    *reinterpret_cast<__half2*>(blk + 32 + off)     = l01;
    *reinterpret_cast<__half2*>(blk + 32 + off + 2) = l23;
}

// ---------------------------------------------------------------------------
// mma.sync / cp.async helpers
// ---------------------------------------------------------------------------
__device__ __forceinline__ uint32_t smem_u32(const void* p) {
    uint32_t a;
    asm("{ .reg .u64 t; cvta.to.shared.u64 t, %1; cvt.u32.u64 %0, t; }"
        : "=r"(a) : "l"(p));
    return a;
}
__device__ __forceinline__ uint64_t gmem_u64(const void* p) {
    uint64_t a;
    asm("cvta.to.global.u64 %0, %1;" : "=l"(a) : "l"(p));
    return a;
}
__device__ __forceinline__ uint32_t sw128(uint32_t o) {
    return o ^ ((o >> 3) & 0x70);
}
__device__ __forceinline__ void cp16(uint32_t dst, uint64_t src) {
    asm volatile("cp.async.cg.shared.global [%0], [%1], 16;"
                 :: "r"(dst), "l"(src) : "memory");
}
__device__ __forceinline__ void cp_commit() {
    asm volatile("cp.async.commit_group;" ::: "memory");
}
template<int n> __device__ __forceinline__ void cp_wait() {
    asm volatile("cp.async.wait_group %0;" :: "n"(n) : "memory");
}
__device__ __forceinline__ void ldsm_x4(uint32_t addr,
                                        uint32_t& r0, uint32_t& r1,
                                        uint32_t& r2, uint32_t& r3) {
    asm volatile("ldmatrix.sync.aligned.m8n8.x4.shared.b16 {%0,%1,%2,%3}, [%4];"
                 : "=r"(r0), "=r"(r1), "=r"(r2), "=r"(r3) : "r"(addr));
}
__device__ __forceinline__ void mma16816(float* c, const uint32_t* a,
                                         uint32_t b0, uint32_t b1) {
    asm volatile(
        "mma.sync.aligned.m16n8k16.row.col.f32.f16.f16.f32 "
        "{%0,%1,%2,%3}, {%4,%5,%6,%7}, {%8,%9}, {%0,%1,%2,%3};"
        : "+f"(c[0]), "+f"(c[1]), "+f"(c[2]), "+f"(c[3])
        : "r"(a[0]), "r"(a[1]), "r"(a[2]), "r"(a[3]), "r"(b0), "r"(b1));
}

// Smem: 3 stages x {A tile 16KB, B tile 16KB}. Tile row = 128B [hi64B|lo64B].
constexpr int STAGE   = 32768;
constexpr int OFF_B   = 16384;
constexpr int SMEM_TOTAL = 3 * STAGE;   // 96 KB -> 2 CTAs/SM

// ---------------------------------------------------------------------------
// Kernel 5: out = H @ Wcat, fp16 2-term split GEMM:
//   Ah*Bh + Al*Bh = A*Bh,  error = A*Bl ~ 2^-11 (fp16 mantissa)
// CTA 128x128, 8 warps (4x2), KC=32, 3-stage cp.async ring, ONE sync/iter.
// ---------------------------------------------------------------------------
__global__ __launch_bounds__(256, 2)
void gemm_kernel(float* __restrict__ out) {
    extern __shared__ char smem[];
    const uint32_t sb = smem_u32(smem);
    const int tid  = threadIdx.x;
    const int wid  = tid >> 5;
    const int lane = tid & 31;
    const int m0   = blockIdx.x * 128;

    const int wm = wid & 3, wn = wid >> 2;
    const int mbase = wm * 32, nbase = wn * 64;
    const int rlane = lane & 15;
    const int klane = (lane >> 4) * 16;

    // cp.async mapping: 2 threads/row, each one 64B half (4x cp16)
    const int crow = tid >> 1;
    const int chalf = (tid & 1) * 64;
    const int arow = (m0 + crow < N_NODES) ? (m0 + crow) : (N_NODES - 1);
    const uint64_t gA = gmem_u64(g_h)  + ((size_t)arow * NCHUNK) * 128 + chalf;
    const uint64_t gB = gmem_u64(g_bt) + ((size_t)crow * NCHUNK) * 128 + chalf;
    const uint32_t rowbase = (uint32_t)(crow * 128 + chalf);

    auto issue = [&](int ch, int s) {
        const uint32_t da = sb + s * STAGE;
        const uint32_t db = da + OFF_B;
        const uint64_t sa = gA + (size_t)ch * 128;
        const uint64_t sbsrc = gB + (size_t)ch * 128;
        // swizzle applied PER 16-byte transfer (matches ldmatrix side)
        #pragma unroll
        for (int i = 0; i < 4; i++) cp16(da + sw128(rowbase + i * 16), sa + i * 16);
        #pragma unroll
        for (int i = 0; i < 4; i++) cp16(db + sw128(rowbase + i * 16), sbsrc + i * 16);
        cp_commit();
    };

    float acc[2][8][4];
    #pragma unroll
    for (int i = 0; i < 2; i++)
        #pragma unroll
        for (int j = 0; j < 8; j++)
            #pragma unroll
            for (int q = 0; q < 4; q++) acc[i][j][q] = 0.f;

    issue(0, 0);
    issue(1, 1);

    for (int ch = 0; ch < NCHUNK; ch++) {
        // One barrier per iter: makes stage-ch data visible AND proves all
        // warps are done reading the stage issue(ch+2) will overwrite.
        if (ch + 1 < NCHUNK) cp_wait<1>(); else cp_wait<0>();
        __syncthreads();
        if (ch + 2 < NCHUNK) issue(ch + 2, (ch + 2) % 3);

        const uint32_t sA = sb + (ch % 3) * STAGE;
        const uint32_t sB = sA + OFF_B;
        #pragma unroll
        for (int kk = 0; kk < 2; kk++) {
            const uint32_t kb = (uint32_t)(kk * 32 + klane);
            uint32_t ahi[2][4], alo[2][4];
            #pragma unroll
            for (int g = 0; g < 2; g++) {
                const uint32_t ro = (uint32_t)((mbase + g * 16 + rlane) * 128);
                ldsm_x4(sA + sw128(ro + kb),      ahi[g][0], ahi[g][1], ahi[g][2], ahi[g][3]);
                ldsm_x4(sA + sw128(ro + 64 + kb), alo[g][0], alo[g][1], alo[g][2], alo[g][3]);
            }
            uint32_t b[4][4];
            #pragma unroll
            for (int nt = 0; nt < 4; nt++) {
                const uint32_t ro = (uint32_t)((nbase + nt * 16 + rlane) * 128);
                ldsm_x4(sB + sw128(ro + kb), b[nt][0], b[nt][1], b[nt][2], b[nt][3]);
            }
            // pass 1: Ah*Bh  (16 MMAs, all distinct accumulators)
            #pragma unroll
            for (int g = 0; g < 2; g++)
                #pragma unroll
                for (int nt = 0; nt < 4; nt++) {
                    mma16816(acc[g][nt * 2 + 0], ahi[g], b[nt][0], b[nt][2]);
                    mma16816(acc[g][nt * 2 + 1], ahi[g], b[nt][1], b[nt][3]);
                }
            // pass 2: Al*Bh
            #pragma unroll
            for (int g = 0; g < 2; g++)
                #pragma unroll
                for (int nt = 0; nt < 4; nt++) {
                    mma16816(acc[g][nt * 2 + 0], alo[g], b[nt][0], b[nt][2]);
                    mma16816(acc[g][nt * 2 + 1], alo[g], b[nt][1], b[nt][3]);
                }
        }
    }

    // ---- epilogue ----
    const int gq = lane >> 2;
    const int tq = lane & 3;
    #pragma unroll
    for (int g = 0; g < 2; g++) {
        const int row_lo = m0 + mbase + g * 16 + gq;
        const int row_hi = row_lo + 8;
        #pragma unroll
        for (int nt = 0; nt < 8; nt++) {
            const int col = nbase + nt * 8 + tq * 2;
            if (row_lo < N_NODES)
                *reinterpret_cast<float2*>(out + (size_t)row_lo * OUT_DIM + col) =
                    make_float2(acc[g][nt][0], acc[g][nt][1]);
            if (row_hi < N_NODES)
                *reinterpret_cast<float2*>(out + (size_t)row_hi * OUT_DIM + col) =
                    make_float2(acc[g][nt][2], acc[g][nt][3]);
        }
    }
}

// ---------------------------------------------------------------------------
// Launch
// ---------------------------------------------------------------------------
extern "C" void kernel_launch(void* const* d_in, const int* in_sizes, int n_in,
                              void* d_out, int out_size) {
    const float* x      = (const float*)d_in[0];
    const float* weight = (const float*)d_in[1];
    const float* selfw  = (const float*)d_in[2];
    const int*   ei     = (const int*)d_in[3];
    const int*   et     = (const int*)d_in[4];
    float*       out    = (float*)d_out;

    cudaFuncSetAttribute(gemm_kernel,
                         cudaFuncAttributeMaxDynamicSharedMemorySize, SMEM_TOTAL);

    zero_cnt_kernel<<<(R_REL * N_NODES + 255) / 256, 256>>>();
    convert_w_kernel<<<(OUT_DIM * K_DIM + 255) / 256, 256>>>(weight, selfw);
    fill_kernel<<<(E_EDGES + 255) / 256, 256>>>(ei, et);

    const int segs = N_NODES * 9;                       // 450000 warps
    agg_kernel<<<(segs + 7) / 8, 256>>>(x);

    gemm_kernel<<<(N_NODES + 127) / 128, 256, SMEM_TOTAL>>>(out);
}

// round 11
// speedup vs baseline: 1.7316x; 1.3537x over previous
#include <cuda_runtime.h>
#include <cuda_fp16.h>
#include <cstdint>

// Problem constants
constexpr int N_NODES = 50000;
constexpr int E_EDGES = 800000;
constexpr int IN_DIM  = 128;
constexpr int OUT_DIM = 128;
constexpr int R_REL   = 8;
constexpr int K_DIM   = IN_DIM * (R_REL + 1);   // 1152
constexpr int KC      = 64;                      // K per chunk (128B fp16 row)
constexpr int NCHUNK  = K_DIM / KC;              // 18
constexpr int MAXDEG  = 64;                      // Poisson(4); ample

// H / W^T storage: per (row, chunk) one 128B block = 64 fp16 (single precision,
// pure fp16 GEMM: error = Al*B + A*Bl ~ 2^-11, measured-class ~3-5e-4).
__device__ uint32_t g_cnt[R_REL * N_NODES];                      // 1.6 MB
__device__ uint32_t g_idx[(size_t)R_REL * N_NODES * MAXDEG];     // 102.4 MB
__device__ __half g_h [(size_t)N_NODES * K_DIM];                 // 115.2 MB
__device__ __half g_bt[(size_t)OUT_DIM * K_DIM];                 // 0.3 MB

// ---------------------------------------------------------------------------
// Kernel 1: zero per-segment counters
// ---------------------------------------------------------------------------
__global__ void zero_cnt_kernel() {
    const int i = blockIdx.x * blockDim.x + threadIdx.x;
    if (i < R_REL * N_NODES) g_cnt[i] = 0u;
}

// ---------------------------------------------------------------------------
// Kernel 2: W^T -> blocked fp16.  BT[n][k] = Wcat[k][n]
// ---------------------------------------------------------------------------
__global__ void convert_w_kernel(const float* __restrict__ weight,
                                 const float* __restrict__ selfw) {
    const int idx = blockIdx.x * blockDim.x + threadIdx.x;
    if (idx >= OUT_DIM * K_DIM) return;
    const int n = idx / K_DIM;
    const int k = idx % K_DIM;
    const float v = (k < IN_DIM)
        ? selfw[(size_t)k * OUT_DIM + n]
        : weight[(size_t)(k - IN_DIM) * OUT_DIM + n];
    const int c = k / KC, p = k % KC;
    g_bt[((size_t)n * NCHUNK + c) * KC + p] = __float2half_rn(v);
}

// ---------------------------------------------------------------------------
// Kernel 3: bucket build (both directed messages per undirected edge)
// ---------------------------------------------------------------------------
__global__ void fill_kernel(const int* __restrict__ ei,
                            const int* __restrict__ et) {
    const int e = blockIdx.x * blockDim.x + threadIdx.x;
    if (e >= E_EDGES) return;
    const int src = ei[e];
    const int dst = ei[E_EDGES + e];
    const int r   = et[e];

    const int seg1 = r * N_NODES + dst;
    uint32_t p1 = atomicAdd(&g_cnt[seg1], 1u);
    if (p1 < MAXDEG) g_idx[(size_t)seg1 * MAXDEG + p1] = (uint32_t)src;

    const int seg2 = r * N_NODES + src;
    uint32_t p2 = atomicAdd(&g_cnt[seg2], 1u);
    if (p2 < MAXDEG) g_idx[(size_t)seg2 * MAXDEG + p2] = (uint32_t)dst;
}

// ---------------------------------------------------------------------------
// Kernel 4: aggregate.  One warp per (v, r9) segment; r9=0 -> x itself,
// r9=1..8 -> mean over relation-(r9-1) neighbors.  Simple gather loop
// (32 regs, max occupancy — occupancy IS the MLP here).  Emits fp16.
// ---------------------------------------------------------------------------
__global__ __launch_bounds__(256)
void agg_kernel(const float* __restrict__ x) {
    const int w = blockIdx.x * 8 + (threadIdx.x >> 5);
    if (w >= N_NODES * 9) return;
    const int lane = threadIdx.x & 31;
    const int v  = w / 9;
    const int r9 = w - v * 9;

    const float4* __restrict__ x4 = reinterpret_cast<const float4*>(x);
    float4 acc = make_float4(0.f, 0.f, 0.f, 0.f);
    float  sc;

    if (r9 == 0) {
        acc = x4[(size_t)v * 32 + lane];
        sc  = 1.0f;
    } else {
        const int seg = (r9 - 1) * N_NODES + v;
        const uint32_t cnt = g_cnt[seg];
        const int d = (cnt < MAXDEG) ? (int)cnt : MAXDEG;
        const uint32_t* __restrict__ lst = g_idx + (size_t)seg * MAXDEG;
        for (int j = 0; j < d; j++) {
            const float4 t = x4[(size_t)lst[j] * 32 + lane];
            acc.x += t.x; acc.y += t.y; acc.z += t.z; acc.w += t.w;
        }
        sc = (cnt > 0u) ? (1.0f / (float)cnt) : 0.0f;
    }

    const __half2 h01 = __floats2half2_rn(acc.x * sc, acc.y * sc);
    const __half2 h23 = __floats2half2_rn(acc.z * sc, acc.w * sc);

    // Each r9 covers 128 floats = chunks 2*r9 and 2*r9+1 (64 fp16 each).
    const int c   = r9 * 2 + (lane >> 4);        // chunk index
    const int off = (lane & 15) * 4;             // fp16 position within chunk
    __half* blk = g_h + ((size_t)v * NCHUNK + c) * KC;
    *reinterpret_cast<__half2*>(blk + off)     = h01;
    *reinterpret_cast<__half2*>(blk + off + 2) = h23;
}

// ---------------------------------------------------------------------------
// mma.sync / cp.async helpers
// ---------------------------------------------------------------------------
__device__ __forceinline__ uint32_t smem_u32(const void* p) {
    uint32_t a;
    asm("{ .reg .u64 t; cvta.to.shared.u64 t, %1; cvt.u32.u64 %0, t; }"
        : "=r"(a) : "l"(p));
    return a;
}
__device__ __forceinline__ uint64_t gmem_u64(const void* p) {
    uint64_t a;
    asm("cvta.to.global.u64 %0, %1;" : "=l"(a) : "l"(p));
    return a;
}
__device__ __forceinline__ uint32_t sw128(uint32_t o) {
    return o ^ ((o >> 3) & 0x70);
}
__device__ __forceinline__ void cp16(uint32_t dst, uint64_t src) {
    asm volatile("cp.async.cg.shared.global [%0], [%1], 16;"
                 :: "r"(dst), "l"(src) : "memory");
}
__device__ __forceinline__ void cp_commit() {
    asm volatile("cp.async.commit_group;" ::: "memory");
}
template<int n> __device__ __forceinline__ void cp_wait() {
    asm volatile("cp.async.wait_group %0;" :: "n"(n) : "memory");
}
__device__ __forceinline__ void ldsm_x4(uint32_t addr,
                                        uint32_t& r0, uint32_t& r1,
                                        uint32_t& r2, uint32_t& r3) {
    asm volatile("ldmatrix.sync.aligned.m8n8.x4.shared.b16 {%0,%1,%2,%3}, [%4];"
                 : "=r"(r0), "=r"(r1), "=r"(r2), "=r"(r3) : "r"(addr));
}
__device__ __forceinline__ void mma16816(float* c, const uint32_t* a,
                                         uint32_t b0, uint32_t b1) {
    asm volatile(
        "mma.sync.aligned.m16n8k16.row.col.f32.f16.f16.f32 "
        "{%0,%1,%2,%3}, {%4,%5,%6,%7}, {%8,%9}, {%0,%1,%2,%3};"
        : "+f"(c[0]), "+f"(c[1]), "+f"(c[2]), "+f"(c[3])
        : "r"(a[0]), "r"(a[1]), "r"(a[2]), "r"(a[3]), "r"(b0), "r"(b1));
}

// Smem: 3 stages x {A tile 16KB, B tile 16KB}. Tile row = 128B (64 fp16).
constexpr int STAGE   = 32768;
constexpr int OFF_B   = 16384;
constexpr int SMEM_TOTAL = 3 * STAGE;   // 96 KB -> 2 CTAs/SM

// ---------------------------------------------------------------------------
// Kernel 5: out = H @ Wcat, pure fp16 GEMM.
// CTA 128x128, 8 warps (4x2), KC=64, 3-stage cp.async ring, ONE sync/iter.
// ---------------------------------------------------------------------------
__global__ __launch_bounds__(256, 2)
void gemm_kernel(float* __restrict__ out) {
    extern __shared__ char smem[];
    const uint32_t sb = smem_u32(smem);
    const int tid  = threadIdx.x;
    const int wid  = tid >> 5;
    const int lane = tid & 31;
    const int m0   = blockIdx.x * 128;

    const int wm = wid & 3, wn = wid >> 2;
    const int mbase = wm * 32, nbase = wn * 64;
    const int rlane = lane & 15;
    const int klane = (lane >> 4) * 16;

    // cp.async mapping: 2 threads/row, each one 64B half (4x cp16)
    const int crow = tid >> 1;
    const int chalf = (tid & 1) * 64;
    const int arow = (m0 + crow < N_NODES) ? (m0 + crow) : (N_NODES - 1);
    const uint64_t gA = gmem_u64(g_h)  + ((size_t)arow * NCHUNK) * 128 + chalf;
    const uint64_t gB = gmem_u64(g_bt) + ((size_t)crow * NCHUNK) * 128 + chalf;
    const uint32_t rowbase = (uint32_t)(crow * 128 + chalf);

    auto issue = [&](int ch, int s) {
        const uint32_t da = sb + s * STAGE;
        const uint32_t db = da + OFF_B;
        const uint64_t sa = gA + (size_t)ch * 128;
        const uint64_t sbsrc = gB + (size_t)ch * 128;
        // swizzle applied PER 16-byte transfer (matches ldmatrix side)
        #pragma unroll
        for (int i = 0; i < 4; i++) cp16(da + sw128(rowbase + i * 16), sa + i * 16);
        #pragma unroll
        for (int i = 0; i < 4; i++) cp16(db + sw128(rowbase + i * 16), sbsrc + i * 16);
        cp_commit();
    };

    float acc[2][8][4];
    #pragma unroll
    for (int i = 0; i < 2; i++)
        #pragma unroll
        for (int j = 0; j < 8; j++)
            #pragma unroll
            for (int q = 0; q < 4; q++) acc[i][j][q] = 0.f;

    issue(0, 0);
    issue(1, 1);

    for (int ch = 0; ch < NCHUNK; ch++) {
        // One barrier per iter: makes stage-ch data visible AND proves all
        // warps are done reading the stage issue(ch+2) will overwrite.
        if (ch + 1 < NCHUNK) cp_wait<1>(); else cp_wait<0>();
        __syncthreads();
        if (ch + 2 < NCHUNK) issue(ch + 2, (ch + 2) % 3);

        const uint32_t sA = sb + (ch % 3) * STAGE;
        const uint32_t sB = sA + OFF_B;
        #pragma unroll
        for (int kk = 0; kk < 4; kk++) {
            const uint32_t kb = (uint32_t)(kk * 32 + klane);
            uint32_t a[2][4];
            #pragma unroll
            for (int g = 0; g < 2; g++) {
                const uint32_t ro = (uint32_t)((mbase + g * 16 + rlane) * 128);
                ldsm_x4(sA + sw128(ro + kb), a[g][0], a[g][1], a[g][2], a[g][3]);
            }
            uint32_t b[4][4];
            #pragma unroll
            for (int nt = 0; nt < 4; nt++) {
                const uint32_t ro = (uint32_t)((nbase + nt * 16 + rlane) * 128);
                ldsm_x4(sB + sw128(ro + kb), b[nt][0], b[nt][1], b[nt][2], b[nt][3]);
            }
            // 16 MMAs, all distinct accumulators
            #pragma unroll
            for (int g = 0; g < 2; g++)
                #pragma unroll
                for (int nt = 0; nt < 4; nt++) {
                    mma16816(acc[g][nt * 2 + 0], a[g], b[nt][0], b[nt][2]);
                    mma16816(acc[g][nt * 2 + 1], a[g], b[nt][1], b[nt][3]);
                }
        }
    }

    // ---- epilogue ----
    const int gq = lane >> 2;
    const int tq = lane & 3;
    #pragma unroll
    for (int g = 0; g < 2; g++) {
        const int row_lo = m0 + mbase + g * 16 + gq;
        const int row_hi = row_lo + 8;
        #pragma unroll
        for (int nt = 0; nt < 8; nt++) {
            const int col = nbase + nt * 8 + tq * 2;
            if (row_lo < N_NODES)
                *reinterpret_cast<float2*>(out + (size_t)row_lo * OUT_DIM + col) =
                    make_float2(acc[g][nt][0], acc[g][nt][1]);
            if (row_hi < N_NODES)
                *reinterpret_cast<float2*>(out + (size_t)row_hi * OUT_DIM + col) =
                    make_float2(acc[g][nt][2], acc[g][nt][3]);
        }
    }
}

// ---------------------------------------------------------------------------
// Launch
// ---------------------------------------------------------------------------
extern "C" void kernel_launch(void* const* d_in, const int* in_sizes, int n_in,
                              void* d_out, int out_size) {
    const float* x      = (const float*)d_in[0];
    const float* weight = (const float*)d_in[1];
    const float* selfw  = (const float*)d_in[2];
    const int*   ei     = (const int*)d_in[3];
    const int*   et     = (const int*)d_in[4];
    float*       out    = (float*)d_out;

    cudaFuncSetAttribute(gemm_kernel,
                         cudaFuncAttributeMaxDynamicSharedMemorySize, SMEM_TOTAL);

    zero_cnt_kernel<<<(R_REL * N_NODES + 255) / 256, 256>>>();
    convert_w_kernel<<<(OUT_DIM * K_DIM + 255) / 256, 256>>>(weight, selfw);
    fill_kernel<<<(E_EDGES + 255) / 256, 256>>>(ei, et);

    const int segs = N_NODES * 9;                       // 450000 warps
    agg_kernel<<<(segs + 7) / 8, 256>>>(x);

    gemm_kernel<<<(N_NODES + 127) / 128, 256, SMEM_TOTAL>>>(out);
}